// round 9
// baseline (speedup 1.0000x reference)
#include <cuda_runtime.h>
#include <math_constants.h>

#define SDIM 2048
#define BDIM 32
#define HDIM 1024

#define KS 16            // k-splits
#define KT (HDIM / KS)   // 64 k per split
#define HT 128           // h per block tile (8 tiles)
#define NSCORE (SDIM * BDIM / 8)   // 8192 streaming blocks

// Scratch (no device allocs allowed)
__device__ float g_part[KS * BDIM * HDIM];  // split-K partials (2 MB)
__device__ float g_u[BDIM * HDIM];          // u = hidden @ W
__device__ float g_scores[BDIM * SDIM];     // scores[b,s]
__device__ unsigned int g_maxbits[BDIM];    // monotone-encoded row max per b
__device__ unsigned int g_count[BDIM];      // warps-done per b (reset by tail)

// order-preserving float <-> uint32 (unsigned compare == float compare)
__device__ __forceinline__ unsigned int f2mono(float f) {
    unsigned int u = __float_as_uint(f);
    return (u & 0x80000000u) ? ~u : (u | 0x80000000u);
}
__device__ __forceinline__ float mono2f(unsigned int u) {
    return __uint_as_float((u & 0x80000000u) ? (u & 0x7FFFFFFFu) : ~u);
}

// ---------------------------------------------------------------------------
// Kernel 1: split-K tiled GEMM. grid (8 h-tiles, 16 k-splits), 512 threads.
// ---------------------------------------------------------------------------
__global__ __launch_bounds__(512) void proj_kernel(
    const float* __restrict__ hidden, const float* __restrict__ W) {
    __shared__ float4 sW[KT * (HT / 4)];   // 32 KB
    __shared__ float  sH[BDIM * KT];       // 8 KB

    const int h0 = blockIdx.x * HT;
    const int k0 = blockIdx.y * KT;
    const int tid = threadIdx.x;

    const float4* __restrict__ Wg = reinterpret_cast<const float4*>(W);
#pragma unroll
    for (int i = 0; i < (KT * HT / 4) / 512; ++i) {   // 4 iters
        int idx = tid + i * 512;
        int kk = idx >> 5;
        int c  = idx & 31;
        sW[idx] = Wg[(size_t)(k0 + kk) * (HDIM / 4) + (h0 >> 2) + c];
    }
#pragma unroll
    for (int i = 0; i < (BDIM * KT) / 512; ++i) {     // 4 iters
        int idx = tid + i * 512;
        int bb = idx >> 6;
        int kk = idx & 63;
        sH[idx] = hidden[bb * HDIM + k0 + kk];
    }
    __syncthreads();

    const int lane = tid & 31;
    const int b0 = (tid >> 5) * 2;      // 16 warps x 2 b

    float4 acc0 = {0,0,0,0}, acc1 = {0,0,0,0};
#pragma unroll 16
    for (int k = 0; k < KT; ++k) {
        float4 w4 = sW[k * 32 + lane];
        float h0v = sH[(b0 + 0) * KT + k];
        float h1v = sH[(b0 + 1) * KT + k];
        acc0.x = fmaf(h0v, w4.x, acc0.x); acc0.y = fmaf(h0v, w4.y, acc0.y);
        acc0.z = fmaf(h0v, w4.z, acc0.z); acc0.w = fmaf(h0v, w4.w, acc0.w);
        acc1.x = fmaf(h1v, w4.x, acc1.x); acc1.y = fmaf(h1v, w4.y, acc1.y);
        acc1.z = fmaf(h1v, w4.z, acc1.z); acc1.w = fmaf(h1v, w4.w, acc1.w);
    }

    float4* __restrict__ part4 = reinterpret_cast<float4*>(
        g_part + (size_t)blockIdx.y * BDIM * HDIM);
    const int hbase4 = (h0 >> 2) + lane;
    part4[(b0 + 0) * (HDIM / 4) + hbase4] = acc0;
    part4[(b0 + 1) * (HDIM / 4) + hbase4] = acc1;
}

// ---------------------------------------------------------------------------
// Kernel 1b: fold split-K partials (fixed order). __ldcs keeps L2 clean.
// ---------------------------------------------------------------------------
__global__ __launch_bounds__(256) void reduce_kernel() {
    const int idx4 = blockIdx.x * 256 + threadIdx.x;   // float4 idx, 0..8191
    float4 s4 = {0, 0, 0, 0};
#pragma unroll
    for (int j = 0; j < KS; ++j) {
        float4 p = __ldcs(reinterpret_cast<const float4*>(
            g_part + (size_t)j * BDIM * HDIM) + idx4);
        s4.x += p.x; s4.y += p.y; s4.z += p.z; s4.w += p.w;
    }
    reinterpret_cast<float4*>(g_u)[idx4] = s4;
}

// ---------------------------------------------------------------------------
// Kernel 2: streaming score + tail-block softmax in ONE launch.
//  bid <  NSCORE: lean stream (identical inner loop); lane0 adds
//                 atomicMax + fence + atomicAdd only (no barriers/smem).
//  bid >= NSCORE: one block per b spins until its 2048 warps are done,
//                 then single-phase softmax (max already known) -> out.
// ---------------------------------------------------------------------------
__global__ __launch_bounds__(256) void score_kernel(const float* __restrict__ enc,
                                                    float* __restrict__ out) {
    const int bid = blockIdx.x;
    const int tid = threadIdx.x;

    if (bid < NSCORE) {
        const int warp = (bid << 3) + (tid >> 5);
        const int lane = tid & 31;
        const int b = warp & (BDIM - 1);
        const int s = warp >> 5;

        const float4* __restrict__ erow =
            reinterpret_cast<const float4*>(enc + (size_t)warp * HDIM);
        const float4* __restrict__ urow =
            reinterpret_cast<const float4*>(g_u + b * HDIM);

        float acc = 0.0f;
#pragma unroll
        for (int j = 0; j < 8; ++j) {
            float4 e = __ldcs(&erow[j * 32 + lane]);   // streaming, evict-first
            float4 u = __ldg(&urow[j * 32 + lane]);    // cached, L2-resident
            acc = fmaf(e.x, u.x, acc);
            acc = fmaf(e.y, u.y, acc);
            acc = fmaf(e.z, u.z, acc);
            acc = fmaf(e.w, u.w, acc);
        }
#pragma unroll
        for (int off = 16; off > 0; off >>= 1)
            acc += __shfl_xor_sync(0xFFFFFFFFu, acc, off);

        if (lane == 0) {
            g_scores[b * SDIM + s] = acc;
            atomicMax(&g_maxbits[b], f2mono(acc));  // order-independent
            __threadfence();                        // release scores+max
            atomicAdd(&g_count[b], 1u);
        }
        return;
    }

    // ----------------- tail: softmax for b = bid - NSCORE -----------------
    const int b = bid - NSCORE;
    __shared__ float svmax;
    __shared__ float sred[8];

    if (tid == 0) {
        while (*((volatile unsigned int*)&g_count[b]) < (unsigned)SDIM)
            __nanosleep(128);
        __threadfence();                    // acquire
        svmax = mono2f(g_maxbits[b]);
        g_count[b] = 0u;                    // self-reset for next replay
        g_maxbits[b] = 0u;
    }
    __syncthreads();

    const float vmax = svmax;
    const int lane = tid & 31;
    const float* __restrict__ row = g_scores + b * SDIM;

    float vals[8];
    float lsum = 0.0f;
#pragma unroll
    for (int j = 0; j < 8; ++j) {
        vals[j] = __expf(row[tid + j * 256] - vmax);
        lsum += vals[j];
    }
#pragma unroll
    for (int off = 16; off > 0; off >>= 1)
        lsum += __shfl_xor_sync(0xFFFFFFFFu, lsum, off);
    if (lane == 0) sred[tid >> 5] = lsum;
    __syncthreads();
    if (tid < 8) {
        float v = sred[tid];
#pragma unroll
        for (int off = 4; off > 0; off >>= 1)
            v += __shfl_xor_sync(0xFFu, v, off);
        sred[0] = v;
    }
    __syncthreads();
    const float inv = 1.0f / sred[0];
#pragma unroll
    for (int j = 0; j < 8; ++j)
        out[b * SDIM + tid + j * 256] = vals[j] * inv;
}

// ---------------------------------------------------------------------------
extern "C" void kernel_launch(void* const* d_in, const int* in_sizes, int n_in,
                              void* d_out, int out_size) {
    const float* hidden = (const float*)d_in[0];  // [B,H]
    const float* enc    = (const float*)d_in[1];  // [S,B,H]
    const float* W      = (const float*)d_in[2];  // [H,H]
    float* out = (float*)d_out;                   // [1,B,S]

    dim3 pg(HDIM / HT, KS);                       // (8, 16)
    proj_kernel<<<pg, 512>>>(hidden, W);
    reduce_kernel<<<(BDIM * HDIM / 4) / 256, 256>>>();   // 32 blocks

    score_kernel<<<NSCORE + BDIM, 256>>>(enc, out);      // 8192 + 32 blocks
}

// round 10
// speedup vs baseline: 1.5397x; 1.5397x over previous
#include <cuda_runtime.h>
#include <math_constants.h>

#define SDIM 2048
#define BDIM 32
#define HDIM 1024

#define KS 32          // k-splits (256 blocks total)
#define KT (HDIM / KS) // 32 k per split
#define HT 128         // h per block tile (8 tiles)

// Scratch (no device allocs allowed)
__device__ float g_part[KS * BDIM * HDIM];  // split-K partials (4 MB)
__device__ float g_u[BDIM * HDIM];          // u = hidden @ W
__device__ float g_scores[BDIM * SDIM];     // scores[b,s]

// ---------------------------------------------------------------------------
// Kernel 1: split-K tiled GEMM u_part = hidden[:, krange] @ W[krange, htile]
// grid (8 h-tiles, 32 k-splits) = 256 blocks, 512 threads (~2 blocks/SM).
// Each thread: 2 b x 4 h outputs, 32-deep k loop.
// ---------------------------------------------------------------------------
__global__ __launch_bounds__(512) void proj_kernel(
    const float* __restrict__ hidden, const float* __restrict__ W) {
    __shared__ float4 sW[KT * (HT / 4)];   // 32k x 32 float4 = 16 KB
    __shared__ float  sH[BDIM * KT];       // 32b x 32k       = 4 KB

    const int h0 = blockIdx.x * HT;
    const int k0 = blockIdx.y * KT;
    const int tid = threadIdx.x;

    const float4* __restrict__ Wg = reinterpret_cast<const float4*>(W);
#pragma unroll
    for (int i = 0; i < (KT * HT / 4) / 512; ++i) {   // 2 iters
        int idx = tid + i * 512;
        int kk = idx >> 5;
        int c  = idx & 31;
        sW[idx] = Wg[(size_t)(k0 + kk) * (HDIM / 4) + (h0 >> 2) + c];
    }
    if (tid < BDIM * KT / 2) {                        // 512 of 1024 elems
        int idx = tid * 2;
        int bb = idx >> 5;                            // /KT(32)
        int kk = idx & 31;
        float2 hv = *reinterpret_cast<const float2*>(hidden + bb * HDIM + k0 + kk);
        sH[idx] = hv.x;
        sH[idx + 1] = hv.y;
    }
    __syncthreads();

    const int lane = tid & 31;          // h4 index (128 h / 4)
    const int b0 = (tid >> 5) * 2;      // 16 warps x 2 b = 32 b

    float4 acc0 = {0,0,0,0}, acc1 = {0,0,0,0};
#pragma unroll
    for (int k = 0; k < KT; ++k) {
        float4 w4 = sW[k * 32 + lane];
        float h0v = sH[(b0 + 0) * KT + k];
        float h1v = sH[(b0 + 1) * KT + k];
        acc0.x = fmaf(h0v, w4.x, acc0.x); acc0.y = fmaf(h0v, w4.y, acc0.y);
        acc0.z = fmaf(h0v, w4.z, acc0.z); acc0.w = fmaf(h0v, w4.w, acc0.w);
        acc1.x = fmaf(h1v, w4.x, acc1.x); acc1.y = fmaf(h1v, w4.y, acc1.y);
        acc1.z = fmaf(h1v, w4.z, acc1.z); acc1.w = fmaf(h1v, w4.w, acc1.w);
    }

    float4* __restrict__ part4 = reinterpret_cast<float4*>(
        g_part + (size_t)blockIdx.y * BDIM * HDIM);
    const int hbase4 = (h0 >> 2) + lane;
    part4[(b0 + 0) * (HDIM / 4) + hbase4] = acc0;
    part4[(b0 + 1) * (HDIM / 4) + hbase4] = acc1;
}

// ---------------------------------------------------------------------------
// Kernel 1b: fold split-K partials (fixed order -> deterministic).
// __ldcs: read-once, keep L2 clean for g_u and the stream.
// ---------------------------------------------------------------------------
__global__ __launch_bounds__(256) void reduce_kernel() {
    const int idx4 = blockIdx.x * 256 + threadIdx.x;   // float4 idx, 0..8191
    float4 s4 = {0, 0, 0, 0};
#pragma unroll
    for (int j = 0; j < KS; ++j) {
        float4 p = __ldcs(reinterpret_cast<const float4*>(
            g_part + (size_t)j * BDIM * HDIM) + idx4);
        s4.x += p.x; s4.y += p.y; s4.z += p.z; s4.w += p.w;
    }
    reinterpret_cast<float4*>(g_u)[idx4] = s4;
}

// ---------------------------------------------------------------------------
// Kernel 2: scores[b,s] = u[b] . enc[s,b,:] — pure 268 MB HBM stream.
// Proven form: no atomics, no prologue, no tail. ~7.2 TB/s achieved.
// ---------------------------------------------------------------------------
__global__ __launch_bounds__(256) void score_kernel(const float* __restrict__ enc) {
    const int warp = (blockIdx.x * blockDim.x + threadIdx.x) >> 5;
    const int lane = threadIdx.x & 31;
    if (warp >= SDIM * BDIM) return;

    const int b = warp & (BDIM - 1);
    const int s = warp >> 5;

    const float4* __restrict__ erow =
        reinterpret_cast<const float4*>(enc + (size_t)warp * HDIM);
    const float4* __restrict__ urow =
        reinterpret_cast<const float4*>(g_u + b * HDIM);

    float acc = 0.0f;
#pragma unroll
    for (int j = 0; j < 8; ++j) {
        float4 e = __ldcs(&erow[j * 32 + lane]);   // streaming, evict-first
        float4 u = __ldg(&urow[j * 32 + lane]);    // cached, L1/L2-resident
        acc = fmaf(e.x, u.x, acc);
        acc = fmaf(e.y, u.y, acc);
        acc = fmaf(e.z, u.z, acc);
        acc = fmaf(e.w, u.w, acc);
    }
#pragma unroll
    for (int off = 16; off > 0; off >>= 1)
        acc += __shfl_xor_sync(0xFFFFFFFFu, acc, off);

    if (lane == 0) g_scores[b * SDIM + s] = acc;
}

// ---------------------------------------------------------------------------
// Kernel 3: softmax over s per b. 32 blocks x 1024 threads.
// (hidden.bias term is constant per b -> invariant under softmax -> dropped.)
// ---------------------------------------------------------------------------
__global__ __launch_bounds__(1024) void softmax_kernel(float* __restrict__ out) {
    const int b = blockIdx.x;
    const int tid = threadIdx.x;
    const float* __restrict__ row = g_scores + b * SDIM;

    __shared__ float sred[32];

    float v0 = row[tid];
    float v1 = row[tid + 1024];
    float vmax = fmaxf(v0, v1);
#pragma unroll
    for (int off = 16; off > 0; off >>= 1)
        vmax = fmaxf(vmax, __shfl_xor_sync(0xFFFFFFFFu, vmax, off));
    if ((tid & 31) == 0) sred[tid >> 5] = vmax;
    __syncthreads();
    if (tid < 32) {
        float v = sred[tid];
#pragma unroll
        for (int off = 16; off > 0; off >>= 1)
            v = fmaxf(v, __shfl_xor_sync(0xFFFFFFFFu, v, off));
        sred[0] = v;
    }
    __syncthreads();
    vmax = sred[0];
    __syncthreads();

    v0 = __expf(v0 - vmax);
    v1 = __expf(v1 - vmax);
    float lsum = v0 + v1;
#pragma unroll
    for (int off = 16; off > 0; off >>= 1)
        lsum += __shfl_xor_sync(0xFFFFFFFFu, lsum, off);
    if ((tid & 31) == 0) sred[tid >> 5] = lsum;
    __syncthreads();
    if (tid < 32) {
        float v = sred[tid];
#pragma unroll
        for (int off = 16; off > 0; off >>= 1)
            v += __shfl_xor_sync(0xFFFFFFFFu, v, off);
        sred[0] = v;
    }
    __syncthreads();
    const float inv = 1.0f / sred[0];

    out[b * SDIM + tid]        = v0 * inv;
    out[b * SDIM + tid + 1024] = v1 * inv;
}

// ---------------------------------------------------------------------------
extern "C" void kernel_launch(void* const* d_in, const int* in_sizes, int n_in,
                              void* d_out, int out_size) {
    const float* hidden = (const float*)d_in[0];  // [B,H]
    const float* enc    = (const float*)d_in[1];  // [S,B,H]
    const float* W      = (const float*)d_in[2];  // [H,H]
    float* out = (float*)d_out;                   // [1,B,S]

    dim3 pg(HDIM / HT, KS);                       // (8, 32) = 256 blocks
    proj_kernel<<<pg, 512>>>(hidden, W);
    reduce_kernel<<<(BDIM * HDIM / 4) / 256, 256>>>();   // 32 blocks

    const int total_warps = SDIM * BDIM;          // 65536
    score_kernel<<<total_warps * 32 / 256, 256>>>(enc);

    softmax_kernel<<<BDIM, 1024>>>(out);
}